// round 1
// baseline (speedup 1.0000x reference)
#include <cuda_runtime.h>
#include <cuda_bf16.h>
#include <cstdint>
#include <cstddef>

// Problem constants
#define BATCH 2
#define SEQ   2048
#define DIM   1024
#define HEADS 16
#define DK    64
#define MROWS (BATCH*SEQ)          // 4096
#define QKVD  (3*DIM)              // 3072

// Scratch (device globals — no allocations allowed)
__device__ float g_qkv[(size_t)MROWS * QKVD];            // [B*S, 3D]
__device__ float g_q[(size_t)BATCH*HEADS*SEQ*DK];        // [B,H,S,DK] (pre-scaled by 1/8)
__device__ float g_k[(size_t)BATCH*HEADS*SEQ*DK];
__device__ float g_v[(size_t)BATCH*HEADS*SEQ*DK];
__device__ float g_ao[(size_t)MROWS * DIM];              // attention out [B*S, D]

// ---------------------------------------------------------------------------
// SGEMM (NT): C[M,N] = A[M,K] * B[N,K]^T, all row-major. M,N % 128 == 0, K % 8 == 0.
// 128x128 tile, 256 threads, 8x8 microtile.
// ---------------------------------------------------------------------------
__global__ __launch_bounds__(256)
void sgemm_nt(const float* __restrict__ A, const float* __restrict__ Bm,
              float* __restrict__ C, int M, int N, int K) {
    __shared__ float As[8][132];
    __shared__ float Bs[8][132];
    const int tid = threadIdx.x;
    const int tx = tid & 15, ty = tid >> 4;
    const int m0 = blockIdx.y * 128, n0 = blockIdx.x * 128;

    float acc[8][8];
#pragma unroll
    for (int i = 0; i < 8; i++)
#pragma unroll
        for (int j = 0; j < 8; j++) acc[i][j] = 0.f;

    const int lr = tid >> 1;            // 0..127
    const int lk = (tid & 1) * 4;       // 0 or 4
    const float* Ap = A + (size_t)(m0 + lr) * K + lk;
    const float* Bp = Bm + (size_t)(n0 + lr) * K + lk;

    for (int kk = 0; kk < K; kk += 8) {
        float4 va = *(const float4*)(Ap + kk);
        float4 vb = *(const float4*)(Bp + kk);
        As[lk + 0][lr] = va.x; As[lk + 1][lr] = va.y;
        As[lk + 2][lr] = va.z; As[lk + 3][lr] = va.w;
        Bs[lk + 0][lr] = vb.x; Bs[lk + 1][lr] = vb.y;
        Bs[lk + 2][lr] = vb.z; Bs[lk + 3][lr] = vb.w;
        __syncthreads();
#pragma unroll
        for (int k = 0; k < 8; k++) {
            float4 a0 = *(const float4*)&As[k][ty * 8];
            float4 a1 = *(const float4*)&As[k][ty * 8 + 4];
            float4 b0 = *(const float4*)&Bs[k][tx * 8];
            float4 b1 = *(const float4*)&Bs[k][tx * 8 + 4];
            float av[8] = {a0.x, a0.y, a0.z, a0.w, a1.x, a1.y, a1.z, a1.w};
            float bv[8] = {b0.x, b0.y, b0.z, b0.w, b1.x, b1.y, b1.z, b1.w};
#pragma unroll
            for (int i = 0; i < 8; i++)
#pragma unroll
                for (int j = 0; j < 8; j++)
                    acc[i][j] = fmaf(av[i], bv[j], acc[i][j]);
        }
        __syncthreads();
    }

#pragma unroll
    for (int i = 0; i < 8; i++) {
        float* cp = C + (size_t)(m0 + ty * 8 + i) * N + n0 + tx * 8;
        *(float4*)cp       = make_float4(acc[i][0], acc[i][1], acc[i][2], acc[i][3]);
        *(float4*)(cp + 4) = make_float4(acc[i][4], acc[i][5], acc[i][6], acc[i][7]);
    }
}

// ---------------------------------------------------------------------------
// RoPE + split/rearrange: g_qkv [B,S,3,H,DK] -> g_q/g_k (RoPE'd, q pre-scaled
// by 1/8) and g_v, each [B,H,S,DK]. One thread per (b,s,h,i) pair, i in 0..31.
// ---------------------------------------------------------------------------
__global__ __launch_bounds__(256)
void rope_kernel(const float* __restrict__ qkv, const int* __restrict__ pos,
                 float* __restrict__ q, float* __restrict__ k, float* __restrict__ v) {
    const int idx = blockIdx.x * 256 + threadIdx.x;   // < 2^21
    const int i = idx & 31;
    const int h = (idx >> 5) & 15;
    const int s = (idx >> 9) & 2047;
    const int b = idx >> 20;

    const size_t base = ((size_t)(b * SEQ + s)) * QKVD + h * DK + 2 * i;
    const float q1 = qkv[base],        q2 = qkv[base + 1];
    const float k1 = qkv[base + DIM],  k2 = qkv[base + DIM + 1];
    const float v1 = qkv[base + 2*DIM], v2 = qkv[base + 2*DIM + 1];

    const float p = (float)pos[s];
    // inv_freq = 10000^(-i/32) = exp2(-i * log2(10000)/32)
    const float freq = exp2f(-(float)i * 0.41524101186092026f);
    float sn, cs;
    sincosf(p * freq, &sn, &cs);

    const size_t ob = ((size_t)((b * HEADS + h) * SEQ + s)) * DK + 2 * i;
    q[ob]     = 0.125f * (q1 * cs - q2 * sn);   // fold 1/sqrt(dk)
    q[ob + 1] = 0.125f * (q1 * sn + q2 * cs);
    k[ob]     = k1 * cs - k2 * sn;
    k[ob + 1] = k1 * sn + k2 * cs;
    v[ob]     = v1;
    v[ob + 1] = v2;
}

// ---------------------------------------------------------------------------
// Causal flash attention, fp32. Block = (qt, h, b), 256 threads.
// BQ = BK = 128, DK = 64. Q,K in smem transposed (d-major), P staged row-major,
// V row-major. Online softmax with 16-lane shuffle reductions.
// ---------------------------------------------------------------------------
#define QT_STRIDE 132
#define V_STRIDE  68
#define ATTN_SMEM_FLOATS (64*QT_STRIDE /*Qt*/ + 64*QT_STRIDE /*Kt*/ + 128*QT_STRIDE /*Ps*/ + 128*V_STRIDE /*Vs*/)
#define ATTN_SMEM_BYTES  (ATTN_SMEM_FLOATS * 4)

__global__ __launch_bounds__(256, 1)
void attn_kernel(const float* __restrict__ gq, const float* __restrict__ gk,
                 const float* __restrict__ gv, float* __restrict__ gao) {
    const int qt = blockIdx.x, h = blockIdx.y, b = blockIdx.z;
    extern __shared__ float sm[];
    float* Qt = sm;                       // [64][132], Qt[d][r]
    float* Kt = Qt + 64 * QT_STRIDE;      // [64][132], Kt[d][c]
    float* Ps = Kt + 64 * QT_STRIDE;      // [128][132], Ps[r][j]
    float* Vs = Ps + 128 * QT_STRIDE;     // [128][68],  Vs[j][c]

    const int tid = threadIdx.x;
    const int tx = tid & 15, ty = tid >> 4;

    const float* qbase = gq + ((size_t)(b * HEADS + h) * SEQ + qt * 128) * DK;
    const float* kb0   = gk + (size_t)(b * HEADS + h) * SEQ * DK;
    const float* vb0   = gv + (size_t)(b * HEADS + h) * SEQ * DK;

    // Load Q tile transposed
    for (int idx = tid; idx < 128 * 16; idx += 256) {
        const int r = idx >> 4, d4 = (idx & 15) * 4;
        float4 vq = *(const float4*)(qbase + r * DK + d4);
        Qt[(d4 + 0) * QT_STRIDE + r] = vq.x;
        Qt[(d4 + 1) * QT_STRIDE + r] = vq.y;
        Qt[(d4 + 2) * QT_STRIDE + r] = vq.z;
        Qt[(d4 + 3) * QT_STRIDE + r] = vq.w;
    }

    float O[8][4];
    float mrow[8], lrow[8];
#pragma unroll
    for (int i = 0; i < 8; i++) {
        mrow[i] = -1e30f; lrow[i] = 0.f;
#pragma unroll
        for (int c = 0; c < 4; c++) O[i][c] = 0.f;
    }

    for (int kt = 0; kt <= qt; kt++) {
        __syncthreads();   // prev iter done with Kt/Vs/Ps; Qt load done (first iter)
        for (int idx = tid; idx < 128 * 16; idx += 256) {
            const int r = idx >> 4, d4 = (idx & 15) * 4;
            float4 vk = *(const float4*)(kb0 + (size_t)(kt * 128 + r) * DK + d4);
            Kt[(d4 + 0) * QT_STRIDE + r] = vk.x;
            Kt[(d4 + 1) * QT_STRIDE + r] = vk.y;
            Kt[(d4 + 2) * QT_STRIDE + r] = vk.z;
            Kt[(d4 + 3) * QT_STRIDE + r] = vk.w;
            float4 vv = *(const float4*)(vb0 + (size_t)(kt * 128 + r) * DK + d4);
            *(float4*)(Vs + r * V_STRIDE + d4) = vv;
        }
        __syncthreads();

        // S = (Q*scale) @ K^T   (scale already folded into Q)
        float acc[8][8];
#pragma unroll
        for (int i = 0; i < 8; i++)
#pragma unroll
            for (int j = 0; j < 8; j++) acc[i][j] = 0.f;

#pragma unroll 8
        for (int d = 0; d < 64; d++) {
            float4 a0 = *(const float4*)(Qt + d * QT_STRIDE + ty * 8);
            float4 a1 = *(const float4*)(Qt + d * QT_STRIDE + ty * 8 + 4);
            float4 b0 = *(const float4*)(Kt + d * QT_STRIDE + tx * 8);
            float4 b1 = *(const float4*)(Kt + d * QT_STRIDE + tx * 8 + 4);
            float av[8] = {a0.x, a0.y, a0.z, a0.w, a1.x, a1.y, a1.z, a1.w};
            float bv[8] = {b0.x, b0.y, b0.z, b0.w, b1.x, b1.y, b1.z, b1.w};
#pragma unroll
            for (int i = 0; i < 8; i++)
#pragma unroll
                for (int j = 0; j < 8; j++)
                    acc[i][j] = fmaf(av[i], bv[j], acc[i][j]);
        }

        // Causal mask on the diagonal tile
        if (kt == qt) {
#pragma unroll
            for (int i = 0; i < 8; i++)
#pragma unroll
                for (int j = 0; j < 8; j++)
                    if (tx * 8 + j > ty * 8 + i) acc[i][j] = -1e30f;
        }

        // Online softmax: row reductions across the 16 tx-threads (lanes 0-15 / 16-31)
        float fac[8];
#pragma unroll
        for (int i = 0; i < 8; i++) {
            float mx = acc[i][0];
#pragma unroll
            for (int j = 1; j < 8; j++) mx = fmaxf(mx, acc[i][j]);
#pragma unroll
            for (int o = 1; o < 16; o <<= 1)
                mx = fmaxf(mx, __shfl_xor_sync(0xffffffffu, mx, o));
            const float mnew = fmaxf(mrow[i], mx);
            fac[i] = __expf(mrow[i] - mnew);
            mrow[i] = mnew;
            float ssum = 0.f;
#pragma unroll
            for (int j = 0; j < 8; j++) {
                const float pv = __expf(acc[i][j] - mnew);
                acc[i][j] = pv;
                ssum += pv;
            }
#pragma unroll
            for (int o = 1; o < 16; o <<= 1)
                ssum += __shfl_xor_sync(0xffffffffu, ssum, o);
            lrow[i] = lrow[i] * fac[i] + ssum;
#pragma unroll
            for (int c = 0; c < 4; c++) O[i][c] *= fac[i];
        }

        // Stage P row-major (conflict-free float4 stores)
#pragma unroll
        for (int i = 0; i < 8; i++) {
            float* pp = Ps + (ty * 8 + i) * QT_STRIDE + tx * 8;
            *(float4*)pp       = make_float4(acc[i][0], acc[i][1], acc[i][2], acc[i][3]);
            *(float4*)(pp + 4) = make_float4(acc[i][4], acc[i][5], acc[i][6], acc[i][7]);
        }
        __syncthreads();

        // O += P @ V
        for (int j = 0; j < 128; j += 4) {
            float a_s[8][4];
#pragma unroll
            for (int i = 0; i < 8; i++) {
                float4 t = *(const float4*)(Ps + (ty * 8 + i) * QT_STRIDE + j);
                a_s[i][0] = t.x; a_s[i][1] = t.y; a_s[i][2] = t.z; a_s[i][3] = t.w;
            }
#pragma unroll
            for (int jj = 0; jj < 4; jj++) {
                float4 bv = *(const float4*)(Vs + (j + jj) * V_STRIDE + tx * 4);
#pragma unroll
                for (int i = 0; i < 8; i++) {
                    O[i][0] = fmaf(a_s[i][jj], bv.x, O[i][0]);
                    O[i][1] = fmaf(a_s[i][jj], bv.y, O[i][1]);
                    O[i][2] = fmaf(a_s[i][jj], bv.z, O[i][2]);
                    O[i][3] = fmaf(a_s[i][jj], bv.w, O[i][3]);
                }
            }
        }
    }

    // Normalize and write out: gao[b*S + srow][h*64 + tx*4 .. +3]
#pragma unroll
    for (int i = 0; i < 8; i++) {
        const float inv = 1.0f / lrow[i];
        const int srow = qt * 128 + ty * 8 + i;
        float4 o4 = make_float4(O[i][0] * inv, O[i][1] * inv, O[i][2] * inv, O[i][3] * inv);
        *(float4*)(gao + ((size_t)b * SEQ + srow) * DIM + h * DK + tx * 4) = o4;
    }
}

// ---------------------------------------------------------------------------
extern "C" void kernel_launch(void* const* d_in, const int* in_sizes, int n_in,
                              void* d_out, int out_size) {
    const float* x    = (const float*)d_in[0];
    const int*   pos  = (const int*)d_in[1];
    const float* wqkv = (const float*)d_in[2];
    const float* wout = (const float*)d_in[3];
    float* out = (float*)d_out;

    float *qkv, *q, *k, *v, *ao;
    cudaGetSymbolAddress((void**)&qkv, g_qkv);
    cudaGetSymbolAddress((void**)&q,   g_q);
    cudaGetSymbolAddress((void**)&k,   g_k);
    cudaGetSymbolAddress((void**)&v,   g_v);
    cudaGetSymbolAddress((void**)&ao,  g_ao);

    // 1) QKV projection: [4096,3072] = x[4096,1024] @ w_qkv[3072,1024]^T
    sgemm_nt<<<dim3(QKVD / 128, MROWS / 128), 256>>>(x, wqkv, qkv, MROWS, QKVD, DIM);

    // 2) RoPE + split to [B,H,S,DK]
    rope_kernel<<<(BATCH * SEQ * HEADS * 32) / 256, 256>>>(qkv, pos, q, k, v);

    // 3) Causal flash attention
    cudaFuncSetAttribute(attn_kernel, cudaFuncAttributeMaxDynamicSharedMemorySize,
                         ATTN_SMEM_BYTES);
    attn_kernel<<<dim3(SEQ / 128, HEADS, BATCH), 256, ATTN_SMEM_BYTES>>>(q, k, v, ao);

    // 4) Output projection: [4096,1024] = ao @ w_out[1024,1024]^T
    sgemm_nt<<<dim3(DIM / 128, MROWS / 128), 256>>>(ao, wout, out, MROWS, DIM, DIM);
}

// round 3
// speedup vs baseline: 1.6274x; 1.6274x over previous
#include <cuda_runtime.h>
#include <cuda_bf16.h>
#include <cstdint>
#include <cstddef>

// Problem constants
#define BATCH 2
#define SEQ   2048
#define DIM   1024
#define HEADS 16
#define DK    64
#define MROWS (BATCH*SEQ)          // 4096
#define QKVD  (3*DIM)              // 3072

// ---------------- scratch (device globals; no allocations allowed) ----------
__device__ float g_qkv[(size_t)MROWS * QKVD];
__device__ float g_q[(size_t)BATCH*HEADS*SEQ*DK];
__device__ float g_k[(size_t)BATCH*HEADS*SEQ*DK];
__device__ float g_v[(size_t)BATCH*HEADS*SEQ*DK];
__device__ float g_ao[(size_t)MROWS * DIM];

// split-bf16 operands
__device__ __nv_bfloat16 g_xhi[(size_t)MROWS*DIM],  g_xlo[(size_t)MROWS*DIM];
__device__ __nv_bfloat16 g_w1hi[(size_t)QKVD*DIM],  g_w1lo[(size_t)QKVD*DIM];
__device__ __nv_bfloat16 g_w2hi[(size_t)DIM*DIM],   g_w2lo[(size_t)DIM*DIM];
__device__ __nv_bfloat16 g_aohi[(size_t)MROWS*DIM], g_aolo[(size_t)MROWS*DIM];

__device__ __forceinline__ uint32_t smem_u32(const void* p) {
    return (uint32_t)__cvta_generic_to_shared(p);
}

// ---------------------------------------------------------------------------
// fp32 -> (bf16 hi, bf16 lo) split.  x = hi + lo + O(2^-18 |x|)
// ---------------------------------------------------------------------------
__global__ __launch_bounds__(256)
void split_bf16_kernel(const float* __restrict__ in, __nv_bfloat16* __restrict__ hi,
                       __nv_bfloat16* __restrict__ lo, int n4) {
    const int i = blockIdx.x * 256 + threadIdx.x;
    if (i >= n4) return;
    float4 v = ((const float4*)in)[i];
    __nv_bfloat16 h0 = __float2bfloat16(v.x);
    __nv_bfloat16 h1 = __float2bfloat16(v.y);
    __nv_bfloat16 h2 = __float2bfloat16(v.z);
    __nv_bfloat16 h3 = __float2bfloat16(v.w);
    __nv_bfloat16 l0 = __float2bfloat16(v.x - __bfloat162float(h0));
    __nv_bfloat16 l1 = __float2bfloat16(v.y - __bfloat162float(h1));
    __nv_bfloat16 l2 = __float2bfloat16(v.z - __bfloat162float(h2));
    __nv_bfloat16 l3 = __float2bfloat16(v.w - __bfloat162float(h3));
    ((__nv_bfloat162*)hi)[2*i]   = __nv_bfloat162(h0, h1);
    ((__nv_bfloat162*)hi)[2*i+1] = __nv_bfloat162(h2, h3);
    ((__nv_bfloat162*)lo)[2*i]   = __nv_bfloat162(l0, l1);
    ((__nv_bfloat162*)lo)[2*i+1] = __nv_bfloat162(l2, l3);
}

// ---------------------------------------------------------------------------
// Split-bf16 HMMA GEMM (portable mma.sync path; no sm_103a-gated PTX).
// C[M,N] = (Ah+Al)[M,K] * (Bh+Bl)[N,K]^T   (drop Al*Bl term)
// CTA tile 128x128, 8 warps of 64x32, K-chunk 64, cp.async double buffer.
// Smem rows padded to 144B -> conflict-free ldmatrix.
// ---------------------------------------------------------------------------
#define ROW_BYTES   144                   // 64 bf16 = 128B data + 16B pad
#define TILE_BYTES  (128 * ROW_BYTES)     // 18432
#define STAGE_BYTES (4 * TILE_BYTES)      // Ah, Al, Bh, Bl
#define GEMM_SMEM   (2 * STAGE_BYTES)     // 147456

__device__ __forceinline__ void ldsm_x4(uint32_t& r0, uint32_t& r1, uint32_t& r2,
                                        uint32_t& r3, uint32_t addr) {
    asm volatile("ldmatrix.sync.aligned.m8n8.x4.shared.b16 {%0,%1,%2,%3}, [%4];"
                 : "=r"(r0), "=r"(r1), "=r"(r2), "=r"(r3) : "r"(addr));
}
__device__ __forceinline__ void ldsm_x2(uint32_t& r0, uint32_t& r1, uint32_t addr) {
    asm volatile("ldmatrix.sync.aligned.m8n8.x2.shared.b16 {%0,%1}, [%2];"
                 : "=r"(r0), "=r"(r1) : "r"(addr));
}
__device__ __forceinline__ void mma_bf16(float* c, const uint32_t* a, const uint32_t* b) {
    asm volatile(
        "mma.sync.aligned.m16n8k16.row.col.f32.bf16.bf16.f32 "
        "{%0,%1,%2,%3}, {%4,%5,%6,%7}, {%8,%9}, {%0,%1,%2,%3};"
        : "+f"(c[0]), "+f"(c[1]), "+f"(c[2]), "+f"(c[3])
        : "r"(a[0]), "r"(a[1]), "r"(a[2]), "r"(a[3]), "r"(b[0]), "r"(b[1]));
}

__global__ __launch_bounds__(256, 1)
void mma_gemm_nt(const __nv_bfloat16* __restrict__ Ahi, const __nv_bfloat16* __restrict__ Alo,
                 const __nv_bfloat16* __restrict__ Bhi, const __nv_bfloat16* __restrict__ Blo,
                 float* __restrict__ C, int M, int N, int K) {
    extern __shared__ __align__(128) char smem[];
    const int tid = threadIdx.x;
    const int lane = tid & 31, wid = tid >> 5;
    const int wm = wid & 1, wn = wid >> 1;          // warp tile: 64x32
    const int m0 = blockIdx.y * 128, n0 = blockIdx.x * 128;
    const int nchunks = K >> 6;

    const __nv_bfloat16* srcs[4] = {Ahi, Alo, Bhi, Blo};

    // ---- async stage loader (16B cp.async x 16 per thread) ----
    auto load_stage = [&](int s, int c) {
        const int k0 = c << 6;
        char* st = smem + s * STAGE_BYTES;
#pragma unroll
        for (int o = 0; o < 4; o++) {
            const __nv_bfloat16* src = srcs[o];
            const int rb = (o < 2) ? m0 : n0;
#pragma unroll
            for (int i = 0; i < 4; i++) {
                const int idx = tid + i * 256;
                const int r = idx >> 3, cc = idx & 7;
                const uint32_t dst = smem_u32(st + o * TILE_BYTES + r * ROW_BYTES + cc * 16);
                const void* g = src + (size_t)(rb + r) * K + k0 + cc * 8;
                asm volatile("cp.async.cg.shared.global [%0], [%1], 16;"
                             :: "r"(dst), "l"(g));
            }
        }
        asm volatile("cp.async.commit_group;" ::: "memory");
    };

    float acc[4][4][4];
#pragma unroll
    for (int mt = 0; mt < 4; mt++)
#pragma unroll
        for (int nt = 0; nt < 4; nt++)
#pragma unroll
            for (int e = 0; e < 4; e++) acc[mt][nt][e] = 0.f;

    load_stage(0, 0);

    for (int c = 0; c < nchunks; c++) {
        const int s = c & 1;
        const bool has_next = (c + 1 < nchunks);
        if (has_next) load_stage(s ^ 1, c + 1);
        if (has_next) asm volatile("cp.async.wait_group 1;" ::: "memory");
        else          asm volatile("cp.async.wait_group 0;" ::: "memory");
        __syncthreads();

        const char* st = smem + s * STAGE_BYTES;
        const uint32_t aBaseH = smem_u32(st) +
            (wm * 64 + (lane & 15)) * ROW_BYTES + ((lane >> 4) & 1) * 16;
        const uint32_t aBaseL = aBaseH + TILE_BYTES;
        const uint32_t bBaseH = smem_u32(st + 2 * TILE_BYTES) +
            (wn * 32 + (lane & 7)) * ROW_BYTES + ((lane >> 3) & 1) * 16;
        const uint32_t bBaseL = bBaseH + TILE_BYTES;

#pragma unroll
        for (int ks = 0; ks < 4; ks++) {
            uint32_t ah[4][4], al[4][4], bh[4][2], bl[4][2];
#pragma unroll
            for (int mt = 0; mt < 4; mt++) {
                const uint32_t off = mt * 16 * ROW_BYTES + ks * 32;
                ldsm_x4(ah[mt][0], ah[mt][1], ah[mt][2], ah[mt][3], aBaseH + off);
                ldsm_x4(al[mt][0], al[mt][1], al[mt][2], al[mt][3], aBaseL + off);
            }
#pragma unroll
            for (int nt = 0; nt < 4; nt++) {
                const uint32_t off = nt * 8 * ROW_BYTES + ks * 32;
                ldsm_x2(bh[nt][0], bh[nt][1], bBaseH + off);
                ldsm_x2(bl[nt][0], bl[nt][1], bBaseL + off);
            }
#pragma unroll
            for (int mt = 0; mt < 4; mt++)
#pragma unroll
                for (int nt = 0; nt < 4; nt++) {
                    mma_bf16(acc[mt][nt], ah[mt], bh[nt]);
                    mma_bf16(acc[mt][nt], ah[mt], bl[nt]);
                    mma_bf16(acc[mt][nt], al[mt], bh[nt]);
                }
        }
        __syncthreads();
    }

    // epilogue: direct fp32 store
#pragma unroll
    for (int mt = 0; mt < 4; mt++)
#pragma unroll
        for (int nt = 0; nt < 4; nt++) {
            const int row = m0 + wm * 64 + mt * 16 + (lane >> 2);
            const int col = n0 + wn * 32 + nt * 8 + (lane & 3) * 2;
            *(float2*)&C[(size_t)row * N + col] =
                make_float2(acc[mt][nt][0], acc[mt][nt][1]);
            *(float2*)&C[(size_t)(row + 8) * N + col] =
                make_float2(acc[mt][nt][2], acc[mt][nt][3]);
        }
}

// ---------------------------------------------------------------------------
// RoPE + split/rearrange: g_qkv [B,S,3,H,DK] -> q/k/v [B,H,S,DK]
// ---------------------------------------------------------------------------
__global__ __launch_bounds__(256)
void rope_kernel(const float* __restrict__ qkv, const int* __restrict__ pos,
                 float* __restrict__ q, float* __restrict__ k, float* __restrict__ v) {
    const int idx = blockIdx.x * 256 + threadIdx.x;
    const int i = idx & 31;
    const int h = (idx >> 5) & 15;
    const int s = (idx >> 9) & 2047;
    const int b = idx >> 20;

    const size_t base = ((size_t)(b * SEQ + s)) * QKVD + h * DK + 2 * i;
    const float q1 = qkv[base],         q2 = qkv[base + 1];
    const float k1 = qkv[base + DIM],   k2 = qkv[base + DIM + 1];
    const float v1 = qkv[base + 2*DIM], v2 = qkv[base + 2*DIM + 1];

    const float p = (float)pos[s];
    const float freq = exp2f(-(float)i * 0.41524101186092026f);
    float sn, cs;
    sincosf(p * freq, &sn, &cs);

    const size_t ob = ((size_t)((b * HEADS + h) * SEQ + s)) * DK + 2 * i;
    q[ob]     = 0.125f * (q1 * cs - q2 * sn);
    q[ob + 1] = 0.125f * (q1 * sn + q2 * cs);
    k[ob]     = k1 * cs - k2 * sn;
    k[ob + 1] = k1 * sn + k2 * cs;
    v[ob]     = v1;
    v[ob + 1] = v2;
}

// ---------------------------------------------------------------------------
// Causal flash attention, fp32 (unchanged from R1 — known good)
// ---------------------------------------------------------------------------
#define QT_STRIDE 132
#define V_STRIDE  68
#define ATTN_SMEM_FLOATS (64*QT_STRIDE + 64*QT_STRIDE + 128*QT_STRIDE + 128*V_STRIDE)
#define ATTN_SMEM_BYTES  (ATTN_SMEM_FLOATS * 4)

__global__ __launch_bounds__(256, 1)
void attn_kernel(const float* __restrict__ gq, const float* __restrict__ gk,
                 const float* __restrict__ gv, float* __restrict__ gao) {
    const int qt = blockIdx.x, h = blockIdx.y, b = blockIdx.z;
    extern __shared__ float sm[];
    float* Qt = sm;
    float* Kt = Qt + 64 * QT_STRIDE;
    float* Ps = Kt + 64 * QT_STRIDE;
    float* Vs = Ps + 128 * QT_STRIDE;

    const int tid = threadIdx.x;
    const int tx = tid & 15, ty = tid >> 4;

    const float* qbase = gq + ((size_t)(b * HEADS + h) * SEQ + qt * 128) * DK;
    const float* kb0   = gk + (size_t)(b * HEADS + h) * SEQ * DK;
    const float* vb0   = gv + (size_t)(b * HEADS + h) * SEQ * DK;

    for (int idx = tid; idx < 128 * 16; idx += 256) {
        const int r = idx >> 4, d4 = (idx & 15) * 4;
        float4 vq = *(const float4*)(qbase + r * DK + d4);
        Qt[(d4 + 0) * QT_STRIDE + r] = vq.x;
        Qt[(d4 + 1) * QT_STRIDE + r] = vq.y;
        Qt[(d4 + 2) * QT_STRIDE + r] = vq.z;
        Qt[(d4 + 3) * QT_STRIDE + r] = vq.w;
    }

    float O[8][4];
    float mrow[8], lrow[8];
#pragma unroll
    for (int i = 0; i < 8; i++) {
        mrow[i] = -1e30f; lrow[i] = 0.f;
#pragma unroll
        for (int c = 0; c < 4; c++) O[i][c] = 0.f;
    }

    for (int kt = 0; kt <= qt; kt++) {
        __syncthreads();
        for (int idx = tid; idx < 128 * 16; idx += 256) {
            const int r = idx >> 4, d4 = (idx & 15) * 4;
            float4 vk = *(const float4*)(kb0 + (size_t)(kt * 128 + r) * DK + d4);
            Kt[(d4 + 0) * QT_STRIDE + r] = vk.x;
            Kt[(d4 + 1) * QT_STRIDE + r] = vk.y;
            Kt[(d4 + 2) * QT_STRIDE + r] = vk.z;
            Kt[(d4 + 3) * QT_STRIDE + r] = vk.w;
            float4 vv = *(const float4*)(vb0 + (size_t)(kt * 128 + r) * DK + d4);
            *(float4*)(Vs + r * V_STRIDE + d4) = vv;
        }
        __syncthreads();

        float acc[8][8];
#pragma unroll
        for (int i = 0; i < 8; i++)
#pragma unroll
            for (int j = 0; j < 8; j++) acc[i][j] = 0.f;

#pragma unroll 8
        for (int d = 0; d < 64; d++) {
            float4 a0 = *(const float4*)(Qt + d * QT_STRIDE + ty * 8);
            float4 a1 = *(const float4*)(Qt + d * QT_STRIDE + ty * 8 + 4);
            float4 b0 = *(const float4*)(Kt + d * QT_STRIDE + tx * 8);
            float4 b1 = *(const float4*)(Kt + d * QT_STRIDE + tx * 8 + 4);
            float av[8] = {a0.x, a0.y, a0.z, a0.w, a1.x, a1.y, a1.z, a1.w};
            float bv[8] = {b0.x, b0.y, b0.z, b0.w, b1.x, b1.y, b1.z, b1.w};
#pragma unroll
            for (int i = 0; i < 8; i++)
#pragma unroll
                for (int j = 0; j < 8; j++)
                    acc[i][j] = fmaf(av[i], bv[j], acc[i][j]);
        }

        if (kt == qt) {
#pragma unroll
            for (int i = 0; i < 8; i++)
#pragma unroll
                for (int j = 0; j < 8; j++)
                    if (tx * 8 + j > ty * 8 + i) acc[i][j] = -1e30f;
        }

        float fac[8];
#pragma unroll
        for (int i = 0; i < 8; i++) {
            float mx = acc[i][0];
#pragma unroll
            for (int j = 1; j < 8; j++) mx = fmaxf(mx, acc[i][j]);
#pragma unroll
            for (int o = 1; o < 16; o <<= 1)
                mx = fmaxf(mx, __shfl_xor_sync(0xffffffffu, mx, o));
            const float mnew = fmaxf(mrow[i], mx);
            fac[i] = __expf(mrow[i] - mnew);
            mrow[i] = mnew;
            float ssum = 0.f;
#pragma unroll
            for (int j = 0; j < 8; j++) {
                const float pv = __expf(acc[i][j] - mnew);
                acc[i][j] = pv;
                ssum += pv;
            }
#pragma unroll
            for (int o = 1; o < 16; o <<= 1)
                ssum += __shfl_xor_sync(0xffffffffu, ssum, o);
            lrow[i] = lrow[i] * fac[i] + ssum;
#pragma unroll
            for (int c = 0; c < 4; c++) O[i][c] *= fac[i];
        }

#pragma unroll
        for (int i = 0; i < 8; i++) {
            float* pp = Ps + (ty * 8 + i) * QT_STRIDE + tx * 8;
            *(float4*)pp       = make_float4(acc[i][0], acc[i][1], acc[i][2], acc[i][3]);
            *(float4*)(pp + 4) = make_float4(acc[i][4], acc[i][5], acc[i][6], acc[i][7]);
        }
        __syncthreads();

        for (int j = 0; j < 128; j += 4) {
            float a_s[8][4];
#pragma unroll
            for (int i = 0; i < 8; i++) {
                float4 t = *(const float4*)(Ps + (ty * 8 + i) * QT_STRIDE + j);
                a_s[i][0] = t.x; a_s[i][1] = t.y; a_s[i][2] = t.z; a_s[i][3] = t.w;
            }
#pragma unroll
            for (int jj = 0; jj < 4; jj++) {
                float4 bv = *(const float4*)(Vs + (j + jj) * V_STRIDE + tx * 4);
#pragma unroll
                for (int i = 0; i < 8; i++) {
                    O[i][0] = fmaf(a_s[i][jj], bv.x, O[i][0]);
                    O[i][1] = fmaf(a_s[i][jj], bv.y, O[i][1]);
                    O[i][2] = fmaf(a_s[i][jj], bv.z, O[i][2]);
                    O[i][3] = fmaf(a_s[i][jj], bv.w, O[i][3]);
                }
            }
        }
    }

#pragma unroll
    for (int i = 0; i < 8; i++) {
        const float inv = 1.0f / lrow[i];
        const int srow = qt * 128 + ty * 8 + i;
        float4 o4 = make_float4(O[i][0] * inv, O[i][1] * inv, O[i][2] * inv, O[i][3] * inv);
        *(float4*)(gao + ((size_t)b * SEQ + srow) * DIM + h * DK + tx * 4) = o4;
    }
}

// ---------------------------------------------------------------------------
extern "C" void kernel_launch(void* const* d_in, const int* in_sizes, int n_in,
                              void* d_out, int out_size) {
    const float* x    = (const float*)d_in[0];
    const int*   pos  = (const int*)d_in[1];
    const float* wqkv = (const float*)d_in[2];
    const float* wout = (const float*)d_in[3];
    float* out = (float*)d_out;

    float *qkv, *q, *k, *v, *ao;
    __nv_bfloat16 *xhi, *xlo, *w1hi, *w1lo, *w2hi, *w2lo, *aohi, *aolo;
    cudaGetSymbolAddress((void**)&qkv,  g_qkv);
    cudaGetSymbolAddress((void**)&q,    g_q);
    cudaGetSymbolAddress((void**)&k,    g_k);
    cudaGetSymbolAddress((void**)&v,    g_v);
    cudaGetSymbolAddress((void**)&ao,   g_ao);
    cudaGetSymbolAddress((void**)&xhi,  g_xhi);
    cudaGetSymbolAddress((void**)&xlo,  g_xlo);
    cudaGetSymbolAddress((void**)&w1hi, g_w1hi);
    cudaGetSymbolAddress((void**)&w1lo, g_w1lo);
    cudaGetSymbolAddress((void**)&w2hi, g_w2hi);
    cudaGetSymbolAddress((void**)&w2lo, g_w2lo);
    cudaGetSymbolAddress((void**)&aohi, g_aohi);
    cudaGetSymbolAddress((void**)&aolo, g_aolo);

    cudaFuncSetAttribute(mma_gemm_nt, cudaFuncAttributeMaxDynamicSharedMemorySize,
                         GEMM_SMEM);
    cudaFuncSetAttribute(attn_kernel, cudaFuncAttributeMaxDynamicSharedMemorySize,
                         ATTN_SMEM_BYTES);

    // 0) split inputs/weights to bf16 hi/lo
    split_bf16_kernel<<<(MROWS*DIM/4)/256, 256>>>(x,    xhi,  xlo,  MROWS*DIM/4);
    split_bf16_kernel<<<(QKVD*DIM/4)/256,  256>>>(wqkv, w1hi, w1lo, QKVD*DIM/4);
    split_bf16_kernel<<<(DIM*DIM/4)/256,   256>>>(wout, w2hi, w2lo, DIM*DIM/4);

    // 1) QKV projection (tensor cores, split-bf16)
    mma_gemm_nt<<<dim3(QKVD/128, MROWS/128), 256, GEMM_SMEM>>>(
        xhi, xlo, w1hi, w1lo, qkv, MROWS, QKVD, DIM);

    // 2) RoPE + split to [B,H,S,DK]
    rope_kernel<<<(BATCH * SEQ * HEADS * 32) / 256, 256>>>(qkv, pos, q, k, v);

    // 3) Causal flash attention (fp32)
    attn_kernel<<<dim3(SEQ/128, HEADS, BATCH), 256, ATTN_SMEM_BYTES>>>(q, k, v, ao);

    // 4) split attention output, then output projection (tensor cores)
    split_bf16_kernel<<<(MROWS*DIM/4)/256, 256>>>(ao, aohi, aolo, MROWS*DIM/4);
    mma_gemm_nt<<<dim3(DIM/128, MROWS/128), 256, GEMM_SMEM>>>(
        aohi, aolo, w2hi, w2lo, out, MROWS, DIM, DIM);
}

// round 9
// speedup vs baseline: 2.8167x; 1.7308x over previous
#include <cuda_runtime.h>
#include <cuda_bf16.h>
#include <cstdint>
#include <cstddef>

// Problem constants
#define BATCH 2
#define SEQ   2048
#define DIM   1024
#define HEADS 16
#define DK    64
#define MROWS (BATCH*SEQ)          // 4096
#define QKVD  (3*DIM)              // 3072

// ---------------- scratch (device globals; no allocations allowed) ----------
__device__ float g_qkv[(size_t)MROWS * QKVD];

// split-bf16 operands for projections
__device__ __nv_bfloat16 g_xhi[(size_t)MROWS*DIM],  g_xlo[(size_t)MROWS*DIM];
__device__ __nv_bfloat16 g_w1hi[(size_t)QKVD*DIM],  g_w1lo[(size_t)QKVD*DIM];
__device__ __nv_bfloat16 g_w2hi[(size_t)DIM*DIM],   g_w2lo[(size_t)DIM*DIM];
__device__ __nv_bfloat16 g_aohi[(size_t)MROWS*DIM], g_aolo[(size_t)MROWS*DIM];

// split-bf16 q/k/v, [B,H,S,DK]
#define QKV_ELEMS ((size_t)BATCH*HEADS*SEQ*DK)
__device__ __nv_bfloat16 g_qh[QKV_ELEMS], g_ql[QKV_ELEMS];
__device__ __nv_bfloat16 g_kh[QKV_ELEMS], g_kl[QKV_ELEMS];
__device__ __nv_bfloat16 g_vh[QKV_ELEMS], g_vl[QKV_ELEMS];

__device__ __forceinline__ uint32_t smem_u32(const void* p) {
    return (uint32_t)__cvta_generic_to_shared(p);
}

// ---------------------------------------------------------------------------
// fp32 -> (bf16 hi, bf16 lo) split.  x = hi + lo + O(2^-18 |x|)
// ---------------------------------------------------------------------------
__global__ __launch_bounds__(256)
void split_bf16_kernel(const float* __restrict__ in, __nv_bfloat16* __restrict__ hi,
                       __nv_bfloat16* __restrict__ lo, int n4) {
    const int i = blockIdx.x * 256 + threadIdx.x;
    if (i >= n4) return;
    float4 v = ((const float4*)in)[i];
    __nv_bfloat16 h0 = __float2bfloat16(v.x);
    __nv_bfloat16 h1 = __float2bfloat16(v.y);
    __nv_bfloat16 h2 = __float2bfloat16(v.z);
    __nv_bfloat16 h3 = __float2bfloat16(v.w);
    __nv_bfloat16 l0 = __float2bfloat16(v.x - __bfloat162float(h0));
    __nv_bfloat16 l1 = __float2bfloat16(v.y - __bfloat162float(h1));
    __nv_bfloat16 l2 = __float2bfloat16(v.z - __bfloat162float(h2));
    __nv_bfloat16 l3 = __float2bfloat16(v.w - __bfloat162float(h3));
    ((__nv_bfloat162*)hi)[2*i]   = __nv_bfloat162(h0, h1);
    ((__nv_bfloat162*)hi)[2*i+1] = __nv_bfloat162(h2, h3);
    ((__nv_bfloat162*)lo)[2*i]   = __nv_bfloat162(l0, l1);
    ((__nv_bfloat162*)lo)[2*i+1] = __nv_bfloat162(l2, l3);
}

// ---------------------------------------------------------------------------
// mma.sync helpers (portable, no sm_103a-gated PTX)
// ---------------------------------------------------------------------------
__device__ __forceinline__ void ldsm_x4(uint32_t& r0, uint32_t& r1, uint32_t& r2,
                                        uint32_t& r3, uint32_t addr) {
    asm volatile("ldmatrix.sync.aligned.m8n8.x4.shared.b16 {%0,%1,%2,%3}, [%4];"
                 : "=r"(r0), "=r"(r1), "=r"(r2), "=r"(r3) : "r"(addr));
}
__device__ __forceinline__ void ldsm_x2(uint32_t& r0, uint32_t& r1, uint32_t addr) {
    asm volatile("ldmatrix.sync.aligned.m8n8.x2.shared.b16 {%0,%1}, [%2];"
                 : "=r"(r0), "=r"(r1) : "r"(addr));
}
__device__ __forceinline__ void ldsm_x2_t(uint32_t& r0, uint32_t& r1, uint32_t addr) {
    asm volatile("ldmatrix.sync.aligned.m8n8.x2.trans.shared.b16 {%0,%1}, [%2];"
                 : "=r"(r0), "=r"(r1) : "r"(addr));
}
__device__ __forceinline__ void mma_bf16(float* c, const uint32_t* a, const uint32_t* b) {
    asm volatile(
        "mma.sync.aligned.m16n8k16.row.col.f32.bf16.bf16.f32 "
        "{%0,%1,%2,%3}, {%4,%5,%6,%7}, {%8,%9}, {%0,%1,%2,%3};"
        : "+f"(c[0]), "+f"(c[1]), "+f"(c[2]), "+f"(c[3])
        : "r"(a[0]), "r"(a[1]), "r"(a[2]), "r"(a[3]), "r"(b[0]), "r"(b[1]));
}
__device__ __forceinline__ uint32_t pack_bf2(float a, float b) {
    __nv_bfloat162 t = __floats2bfloat162_rn(a, b);
    return *(uint32_t*)&t;
}

// ---------------------------------------------------------------------------
// Split-bf16 HMMA GEMM (proven in R3)
// ---------------------------------------------------------------------------
#define ROW_BYTES   144
#define TILE_BYTES  (128 * ROW_BYTES)     // 18432
#define STAGE_BYTES (4 * TILE_BYTES)
#define GEMM_SMEM   (2 * STAGE_BYTES)

__global__ __launch_bounds__(256, 1)
void mma_gemm_nt(const __nv_bfloat16* __restrict__ Ahi, const __nv_bfloat16* __restrict__ Alo,
                 const __nv_bfloat16* __restrict__ Bhi, const __nv_bfloat16* __restrict__ Blo,
                 float* __restrict__ C, int M, int N, int K) {
    extern __shared__ __align__(128) char smem[];
    const int tid = threadIdx.x;
    const int lane = tid & 31, wid = tid >> 5;
    const int wm = wid & 1, wn = wid >> 1;
    const int m0 = blockIdx.y * 128, n0 = blockIdx.x * 128;
    const int nchunks = K >> 6;

    const __nv_bfloat16* srcs[4] = {Ahi, Alo, Bhi, Blo};

    auto load_stage = [&](int s, int c) {
        const int k0 = c << 6;
        char* st = smem + s * STAGE_BYTES;
#pragma unroll
        for (int o = 0; o < 4; o++) {
            const __nv_bfloat16* src = srcs[o];
            const int rb = (o < 2) ? m0 : n0;
#pragma unroll
            for (int i = 0; i < 4; i++) {
                const int idx = tid + i * 256;
                const int r = idx >> 3, cc = idx & 7;
                const uint32_t dst = smem_u32(st + o * TILE_BYTES + r * ROW_BYTES + cc * 16);
                const void* g = src + (size_t)(rb + r) * K + k0 + cc * 8;
                asm volatile("cp.async.cg.shared.global [%0], [%1], 16;"
                             :: "r"(dst), "l"(g));
            }
        }
        asm volatile("cp.async.commit_group;" ::: "memory");
    };

    float acc[4][4][4];
#pragma unroll
    for (int mt = 0; mt < 4; mt++)
#pragma unroll
        for (int nt = 0; nt < 4; nt++)
#pragma unroll
            for (int e = 0; e < 4; e++) acc[mt][nt][e] = 0.f;

    load_stage(0, 0);

    for (int c = 0; c < nchunks; c++) {
        const int s = c & 1;
        const bool has_next = (c + 1 < nchunks);
        if (has_next) load_stage(s ^ 1, c + 1);
        if (has_next) asm volatile("cp.async.wait_group 1;" ::: "memory");
        else          asm volatile("cp.async.wait_group 0;" ::: "memory");
        __syncthreads();

        const char* st = smem + s * STAGE_BYTES;
        const uint32_t aBaseH = smem_u32(st) +
            (wm * 64 + (lane & 15)) * ROW_BYTES + ((lane >> 4) & 1) * 16;
        const uint32_t aBaseL = aBaseH + TILE_BYTES;
        const uint32_t bBaseH = smem_u32(st + 2 * TILE_BYTES) +
            (wn * 32 + (lane & 7)) * ROW_BYTES + ((lane >> 3) & 1) * 16;
        const uint32_t bBaseL = bBaseH + TILE_BYTES;

#pragma unroll
        for (int ks = 0; ks < 4; ks++) {
            uint32_t ah[4][4], al[4][4], bh[4][2], bl[4][2];
#pragma unroll
            for (int mt = 0; mt < 4; mt++) {
                const uint32_t off = mt * 16 * ROW_BYTES + ks * 32;
                ldsm_x4(ah[mt][0], ah[mt][1], ah[mt][2], ah[mt][3], aBaseH + off);
                ldsm_x4(al[mt][0], al[mt][1], al[mt][2], al[mt][3], aBaseL + off);
            }
#pragma unroll
            for (int nt = 0; nt < 4; nt++) {
                const uint32_t off = nt * 8 * ROW_BYTES + ks * 32;
                ldsm_x2(bh[nt][0], bh[nt][1], bBaseH + off);
                ldsm_x2(bl[nt][0], bl[nt][1], bBaseL + off);
            }
#pragma unroll
            for (int mt = 0; mt < 4; mt++)
#pragma unroll
                for (int nt = 0; nt < 4; nt++) {
                    mma_bf16(acc[mt][nt], ah[mt], bh[nt]);
                    mma_bf16(acc[mt][nt], ah[mt], bl[nt]);
                    mma_bf16(acc[mt][nt], al[mt], bh[nt]);
                }
        }
        __syncthreads();
    }

#pragma unroll
    for (int mt = 0; mt < 4; mt++)
#pragma unroll
        for (int nt = 0; nt < 4; nt++) {
            const int row = m0 + wm * 64 + mt * 16 + (lane >> 2);
            const int col = n0 + wn * 32 + nt * 8 + (lane & 3) * 2;
            *(float2*)&C[(size_t)row * N + col] =
                make_float2(acc[mt][nt][0], acc[mt][nt][1]);
            *(float2*)&C[(size_t)(row + 8) * N + col] =
                make_float2(acc[mt][nt][2], acc[mt][nt][3]);
        }
}

// ---------------------------------------------------------------------------
// RoPE + split to bf16 hi/lo: g_qkv [B,S,3,H,DK] -> qh/ql/kh/kl/vh/vl [B,H,S,DK]
// q pre-scaled by 1/8.
// ---------------------------------------------------------------------------
__global__ __launch_bounds__(256)
void rope_split_kernel(const float* __restrict__ qkv, const int* __restrict__ pos,
                       __nv_bfloat16* __restrict__ qh, __nv_bfloat16* __restrict__ ql,
                       __nv_bfloat16* __restrict__ kh, __nv_bfloat16* __restrict__ kl,
                       __nv_bfloat16* __restrict__ vh, __nv_bfloat16* __restrict__ vl) {
    const int idx = blockIdx.x * 256 + threadIdx.x;
    const int i = idx & 31;
    const int h = (idx >> 5) & 15;
    const int s = (idx >> 9) & 2047;
    const int b = idx >> 20;

    const size_t base = ((size_t)(b * SEQ + s)) * QKVD + h * DK + 2 * i;
    const float q1 = qkv[base],         q2 = qkv[base + 1];
    const float k1 = qkv[base + DIM],   k2 = qkv[base + DIM + 1];
    const float v1 = qkv[base + 2*DIM], v2 = qkv[base + 2*DIM + 1];

    const float p = (float)pos[s];
    const float freq = exp2f(-(float)i * 0.41524101186092026f);
    float sn, cs;
    sincosf(p * freq, &sn, &cs);

    const float qe = 0.125f * (q1 * cs - q2 * sn);
    const float qo = 0.125f * (q1 * sn + q2 * cs);
    const float ke = k1 * cs - k2 * sn;
    const float ko = k1 * sn + k2 * cs;

    const size_t ob = ((size_t)((b * HEADS + h) * SEQ + s)) * DK + 2 * i;
#define WRSPLIT(HI, LO, A, B)                                              \
    {                                                                      \
        __nv_bfloat162 h2 = __floats2bfloat162_rn((A), (B));               \
        float2 f = __bfloat1622float2(h2);                                 \
        __nv_bfloat162 l2 = __floats2bfloat162_rn((A) - f.x, (B) - f.y);   \
        *(__nv_bfloat162*)((HI) + ob) = h2;                                \
        *(__nv_bfloat162*)((LO) + ob) = l2;                                \
    }
    WRSPLIT(qh, ql, qe, qo);
    WRSPLIT(kh, kl, ke, ko);
    WRSPLIT(vh, vl, v1, v2);
#undef WRSPLIT
}

// ---------------------------------------------------------------------------
// Tensor-core causal flash attention, split-bf16 (3-term) for S and PV.
// Block = (qt, h, b), 256 threads, 8 warps x 16 q-rows. BQ=BK=128, DK=64.
// Q/K/V staged as bf16 hi/lo, rows padded to 144B. K via ldmatrix, V via
// ldmatrix.trans. Per-warp online softmax. Writes ao as bf16 hi/lo.
// ---------------------------------------------------------------------------
#define AROW 144
#define ATILE (128 * AROW)                // 18432
#define AQ_BYTES (2 * ATILE)              // Qh, Ql
#define AKV_STAGE (4 * ATILE)             // Kh, Kl, Vh, Vl
#define ATTN_SMEM (AQ_BYTES + 2 * AKV_STAGE)  // 184320

__global__ __launch_bounds__(256, 1)
void attn_mma_kernel(const __nv_bfloat16* __restrict__ qh, const __nv_bfloat16* __restrict__ ql,
                     const __nv_bfloat16* __restrict__ kh, const __nv_bfloat16* __restrict__ kl,
                     const __nv_bfloat16* __restrict__ vh, const __nv_bfloat16* __restrict__ vl,
                     __nv_bfloat16* __restrict__ aohi, __nv_bfloat16* __restrict__ aolo) {
    extern __shared__ __align__(128) char sm2[];
    const int qt = blockIdx.x, h = blockIdx.y, b = blockIdx.z;
    const int tid = threadIdx.x, lane = tid & 31, wid = tid >> 5;
    const size_t bh = (size_t)(b * HEADS + h) * SEQ;

    // ---- Q tile (hi/lo), part of async group 0 ----
#pragma unroll
    for (int i = 0; i < 4; i++) {
        const int idx = tid + i * 256;
        const int r = idx >> 3, c = idx & 7;
        const uint32_t d = smem_u32(sm2 + r * AROW + c * 16);
        const size_t g = (bh + (size_t)(qt * 128 + r)) * DK + c * 8;
        asm volatile("cp.async.cg.shared.global [%0], [%1], 16;" :: "r"(d), "l"(qh + g));
        asm volatile("cp.async.cg.shared.global [%0], [%1], 16;" :: "r"(d + ATILE), "l"(ql + g));
    }

    auto load_kv = [&](int s, int j) {
        char* st = sm2 + AQ_BYTES + s * AKV_STAGE;
#pragma unroll
        for (int i = 0; i < 4; i++) {
            const int idx = tid + i * 256;
            const int r = idx >> 3, c = idx & 7;
            const uint32_t d0 = smem_u32(st + r * AROW + c * 16);
            const size_t g = (bh + (size_t)(j * 128 + r)) * DK + c * 8;
            asm volatile("cp.async.cg.shared.global [%0], [%1], 16;" :: "r"(d0), "l"(kh + g));
            asm volatile("cp.async.cg.shared.global [%0], [%1], 16;" :: "r"(d0 + ATILE), "l"(kl + g));
            asm volatile("cp.async.cg.shared.global [%0], [%1], 16;" :: "r"(d0 + 2*ATILE), "l"(vh + g));
            asm volatile("cp.async.cg.shared.global [%0], [%1], 16;" :: "r"(d0 + 3*ATILE), "l"(vl + g));
        }
        asm volatile("cp.async.commit_group;" ::: "memory");
    };
    load_kv(0, 0);   // commits group 0 (includes Q)

    float O[8][4];
#pragma unroll
    for (int nt = 0; nt < 8; nt++)
#pragma unroll
        for (int e = 0; e < 4; e++) O[nt][e] = 0.f;
    float mrow[2] = {-1e30f, -1e30f}, lrow[2] = {0.f, 0.f};

    const uint32_t qB = smem_u32(sm2) + (wid * 16 + (lane & 15)) * AROW + ((lane >> 4) & 1) * 16;

    for (int kt = 0; kt <= qt; kt++) {
        const int s = kt & 1;
        const bool has_next = (kt < qt);
        if (has_next) load_kv(s ^ 1, kt + 1);
        if (has_next) asm volatile("cp.async.wait_group 1;" ::: "memory");
        else          asm volatile("cp.async.wait_group 0;" ::: "memory");
        __syncthreads();

        const char* st = sm2 + AQ_BYTES + s * AKV_STAGE;
        const uint32_t kB = smem_u32(st) + (lane & 7) * AROW + ((lane >> 3) & 1) * 16;
        const uint32_t vB = smem_u32(st + 2 * ATILE) + (lane & 15) * AROW;

        // Q fragments (hi/lo) for all 4 k-steps
        uint32_t qfh[4][4], qfl[4][4];
#pragma unroll
        for (int ks = 0; ks < 4; ks++) {
            ldsm_x4(qfh[ks][0], qfh[ks][1], qfh[ks][2], qfh[ks][3], qB + ks * 32);
            ldsm_x4(qfl[ks][0], qfl[ks][1], qfl[ks][2], qfl[ks][3], qB + ATILE + ks * 32);
        }

        // ---- S = Q K^T (split 3-term) ----
        float sacc[16][4];
#pragma unroll
        for (int nt = 0; nt < 16; nt++)
#pragma unroll
            for (int e = 0; e < 4; e++) sacc[nt][e] = 0.f;

#pragma unroll
        for (int nt = 0; nt < 16; nt++) {
            const uint32_t off = (uint32_t)(nt * 8 * AROW);
#pragma unroll
            for (int ks = 0; ks < 4; ks++) {
                uint32_t kbh[2], kbl[2];
                ldsm_x2(kbh[0], kbh[1], kB + off + ks * 32);
                ldsm_x2(kbl[0], kbl[1], kB + ATILE + off + ks * 32);
                mma_bf16(sacc[nt], qfh[ks], kbh);
                mma_bf16(sacc[nt], qfh[ks], kbl);
                mma_bf16(sacc[nt], qfl[ks], kbh);
            }
        }

        // ---- causal mask on diagonal tile ----
        if (kt == qt) {
            const int r0 = wid * 16 + (lane >> 2);
            const int c0 = 2 * (lane & 3);
#pragma unroll
            for (int nt = 0; nt < 16; nt++) {
                const int cb = nt * 8 + c0;
                if (cb     > r0)     sacc[nt][0] = -1e30f;
                if (cb + 1 > r0)     sacc[nt][1] = -1e30f;
                if (cb     > r0 + 8) sacc[nt][2] = -1e30f;
                if (cb + 1 > r0 + 8) sacc[nt][3] = -1e30f;
            }
        }

        // ---- online softmax (per-warp; quad-lane reductions) ----
#pragma unroll
        for (int rho = 0; rho < 2; rho++) {
            float mx = -1e30f;
#pragma unroll
            for (int nt = 0; nt < 16; nt++)
                mx = fmaxf(mx, fmaxf(sacc[nt][2*rho], sacc[nt][2*rho+1]));
            mx = fmaxf(mx, __shfl_xor_sync(0xffffffffu, mx, 1));
            mx = fmaxf(mx, __shfl_xor_sync(0xffffffffu, mx, 2));
            const float mn = fmaxf(mrow[rho], mx);
            const float fac = __expf(mrow[rho] - mn);
            mrow[rho] = mn;
            float sum = 0.f;
#pragma unroll
            for (int nt = 0; nt < 16; nt++) {
                const float p0 = __expf(sacc[nt][2*rho]   - mn);
                const float p1 = __expf(sacc[nt][2*rho+1] - mn);
                sacc[nt][2*rho] = p0; sacc[nt][2*rho+1] = p1;
                sum += p0 + p1;
            }
            sum += __shfl_xor_sync(0xffffffffu, sum, 1);
            sum += __shfl_xor_sync(0xffffffffu, sum, 2);
            lrow[rho] = lrow[rho] * fac + sum;
#pragma unroll
            for (int nt = 0; nt < 8; nt++) {
                O[nt][2*rho]   *= fac;
                O[nt][2*rho+1] *= fac;
            }
        }

        // ---- O += P V (split 3-term; P split in-register) ----
#pragma unroll
        for (int ks = 0; ks < 8; ks++) {
            const int t0 = 2 * ks, t1 = t0 + 1;
            uint32_t pah[4], pal[4];
            pah[0] = pack_bf2(sacc[t0][0], sacc[t0][1]);
            pah[1] = pack_bf2(sacc[t0][2], sacc[t0][3]);
            pah[2] = pack_bf2(sacc[t1][0], sacc[t1][1]);
            pah[3] = pack_bf2(sacc[t1][2], sacc[t1][3]);
            {
                float2 f0 = __bfloat1622float2(*(__nv_bfloat162*)&pah[0]);
                float2 f1 = __bfloat1622float2(*(__nv_bfloat162*)&pah[1]);
                float2 f2 = __bfloat1622float2(*(__nv_bfloat162*)&pah[2]);
                float2 f3 = __bfloat1622float2(*(__nv_bfloat162*)&pah[3]);
                pal[0] = pack_bf2(sacc[t0][0] - f0.x, sacc[t0][1] - f0.y);
                pal[1] = pack_bf2(sacc[t0][2] - f1.x, sacc[t0][3] - f1.y);
                pal[2] = pack_bf2(sacc[t1][0] - f2.x, sacc[t1][1] - f2.y);
                pal[3] = pack_bf2(sacc[t1][2] - f3.x, sacc[t1][3] - f3.y);
            }
            const uint32_t vrow = vB + (uint32_t)(ks * 16 * AROW);
#pragma unroll
            for (int dt = 0; dt < 8; dt++) {
                uint32_t vbh[2], vbl[2];
                ldsm_x2_t(vbh[0], vbh[1], vrow + dt * 16);
                ldsm_x2_t(vbl[0], vbl[1], vrow + ATILE + dt * 16);
                mma_bf16(O[dt], pah, vbh);
                mma_bf16(O[dt], pah, vbl);
                mma_bf16(O[dt], pal, vbh);
            }
        }
        __syncthreads();
    }

    // ---- epilogue: normalize, split to bf16 hi/lo, write ao ----
#pragma unroll
    for (int rho = 0; rho < 2; rho++) {
        const float inv = 1.0f / lrow[rho];
        const int srow = qt * 128 + wid * 16 + (lane >> 2) + rho * 8;
        const size_t rowoff = ((size_t)b * SEQ + srow) * DIM + h * 64 + 2 * (lane & 3);
#pragma unroll
        for (int nt = 0; nt < 8; nt++) {
            const float o0 = O[nt][2*rho] * inv, o1 = O[nt][2*rho+1] * inv;
            __nv_bfloat162 h2 = __floats2bfloat162_rn(o0, o1);
            float2 f = __bfloat1622float2(h2);
            __nv_bfloat162 l2 = __floats2bfloat162_rn(o0 - f.x, o1 - f.y);
            *(__nv_bfloat162*)(aohi + rowoff + nt * 8) = h2;
            *(__nv_bfloat162*)(aolo + rowoff + nt * 8) = l2;
        }
    }
}

// ---------------------------------------------------------------------------
extern "C" void kernel_launch(void* const* d_in, const int* in_sizes, int n_in,
                              void* d_out, int out_size) {
    const float* x    = (const float*)d_in[0];
    const int*   pos  = (const int*)d_in[1];
    const float* wqkv = (const float*)d_in[2];
    const float* wout = (const float*)d_in[3];
    float* out = (float*)d_out;

    float* qkv;
    __nv_bfloat16 *xhi, *xlo, *w1hi, *w1lo, *w2hi, *w2lo, *aohi, *aolo;
    __nv_bfloat16 *pqh, *pql, *pkh, *pkl, *pvh, *pvl;
    cudaGetSymbolAddress((void**)&qkv,  g_qkv);
    cudaGetSymbolAddress((void**)&xhi,  g_xhi);
    cudaGetSymbolAddress((void**)&xlo,  g_xlo);
    cudaGetSymbolAddress((void**)&w1hi, g_w1hi);
    cudaGetSymbolAddress((void**)&w1lo, g_w1lo);
    cudaGetSymbolAddress((void**)&w2hi, g_w2hi);
    cudaGetSymbolAddress((void**)&w2lo, g_w2lo);
    cudaGetSymbolAddress((void**)&aohi, g_aohi);
    cudaGetSymbolAddress((void**)&aolo, g_aolo);
    cudaGetSymbolAddress((void**)&pqh,  g_qh);
    cudaGetSymbolAddress((void**)&pql,  g_ql);
    cudaGetSymbolAddress((void**)&pkh,  g_kh);
    cudaGetSymbolAddress((void**)&pkl,  g_kl);
    cudaGetSymbolAddress((void**)&pvh,  g_vh);
    cudaGetSymbolAddress((void**)&pvl,  g_vl);

    cudaFuncSetAttribute(mma_gemm_nt, cudaFuncAttributeMaxDynamicSharedMemorySize,
                         GEMM_SMEM);
    cudaFuncSetAttribute(attn_mma_kernel, cudaFuncAttributeMaxDynamicSharedMemorySize,
                         ATTN_SMEM);

    // 0) split inputs/weights to bf16 hi/lo
    split_bf16_kernel<<<(MROWS*DIM/4)/256, 256>>>(x,    xhi,  xlo,  MROWS*DIM/4);
    split_bf16_kernel<<<(QKVD*DIM/4)/256,  256>>>(wqkv, w1hi, w1lo, QKVD*DIM/4);
    split_bf16_kernel<<<(DIM*DIM/4)/256,   256>>>(wout, w2hi, w2lo, DIM*DIM/4);

    // 1) QKV projection (tensor cores, split-bf16)
    mma_gemm_nt<<<dim3(QKVD/128, MROWS/128), 256, GEMM_SMEM>>>(
        xhi, xlo, w1hi, w1lo, qkv, MROWS, QKVD, DIM);

    // 2) RoPE + split q/k/v to bf16 hi/lo [B,H,S,DK]
    rope_split_kernel<<<(BATCH * SEQ * HEADS * 32) / 256, 256>>>(
        qkv, pos, pqh, pql, pkh, pkl, pvh, pvl);

    // 3) Tensor-core causal flash attention (writes ao hi/lo directly)
    attn_mma_kernel<<<dim3(SEQ/128, HEADS, BATCH), 256, ATTN_SMEM>>>(
        pqh, pql, pkh, pkl, pvh, pvl, aohi, aolo);

    // 4) Output projection (tensor cores)
    mma_gemm_nt<<<dim3(DIM/128, MROWS/128), 256, GEMM_SMEM>>>(
        aohi, aolo, w2hi, w2lo, out, MROWS, DIM, DIM);
}

// round 17
// speedup vs baseline: 2.8599x; 1.0154x over previous
#include <cuda_runtime.h>
#include <cuda_bf16.h>
#include <cstdint>
#include <cstddef>

// Problem constants
#define BATCH 2
#define SEQ   2048
#define DIM   1024
#define HEADS 16
#define DK    64
#define MROWS (BATCH*SEQ)          // 4096
#define QKVD  (3*DIM)              // 3072

// ---------------- scratch (device globals; no allocations allowed) ----------
__device__ float g_qkv[(size_t)MROWS * QKVD];

// split-bf16 operands for projections
__device__ __nv_bfloat16 g_xhi[(size_t)MROWS*DIM],  g_xlo[(size_t)MROWS*DIM];
__device__ __nv_bfloat16 g_w1hi[(size_t)QKVD*DIM],  g_w1lo[(size_t)QKVD*DIM];
__device__ __nv_bfloat16 g_w2hi[(size_t)DIM*DIM],   g_w2lo[(size_t)DIM*DIM];
__device__ __nv_bfloat16 g_aohi[(size_t)MROWS*DIM], g_aolo[(size_t)MROWS*DIM];

// split-bf16 q/k/v, [B,H,S,DK]
#define QKV_ELEMS ((size_t)BATCH*HEADS*SEQ*DK)
__device__ __nv_bfloat16 g_qh[QKV_ELEMS], g_ql[QKV_ELEMS];
__device__ __nv_bfloat16 g_kh[QKV_ELEMS], g_kl[QKV_ELEMS];
__device__ __nv_bfloat16 g_vh[QKV_ELEMS], g_vl[QKV_ELEMS];

__device__ __forceinline__ uint32_t smem_u32(const void* p) {
    return (uint32_t)__cvta_generic_to_shared(p);
}

// ---------------------------------------------------------------------------
// fp32 -> (bf16 hi, bf16 lo) split.  x = hi + lo + O(2^-18 |x|)
// ---------------------------------------------------------------------------
__global__ __launch_bounds__(256)
void split_bf16_kernel(const float* __restrict__ in, __nv_bfloat16* __restrict__ hi,
                       __nv_bfloat16* __restrict__ lo, int n4) {
    const int i = blockIdx.x * 256 + threadIdx.x;
    if (i >= n4) return;
    float4 v = ((const float4*)in)[i];
    __nv_bfloat16 h0 = __float2bfloat16(v.x);
    __nv_bfloat16 h1 = __float2bfloat16(v.y);
    __nv_bfloat16 h2 = __float2bfloat16(v.z);
    __nv_bfloat16 h3 = __float2bfloat16(v.w);
    __nv_bfloat16 l0 = __float2bfloat16(v.x - __bfloat162float(h0));
    __nv_bfloat16 l1 = __float2bfloat16(v.y - __bfloat162float(h1));
    __nv_bfloat16 l2 = __float2bfloat16(v.z - __bfloat162float(h2));
    __nv_bfloat16 l3 = __float2bfloat16(v.w - __bfloat162float(h3));
    ((__nv_bfloat162*)hi)[2*i]   = __nv_bfloat162(h0, h1);
    ((__nv_bfloat162*)hi)[2*i+1] = __nv_bfloat162(h2, h3);
    ((__nv_bfloat162*)lo)[2*i]   = __nv_bfloat162(l0, l1);
    ((__nv_bfloat162*)lo)[2*i+1] = __nv_bfloat162(l2, l3);
}

// ---------------------------------------------------------------------------
// mma.sync helpers (portable, no sm_103a-gated PTX)
// ---------------------------------------------------------------------------
__device__ __forceinline__ void ldsm_x4(uint32_t& r0, uint32_t& r1, uint32_t& r2,
                                        uint32_t& r3, uint32_t addr) {
    asm volatile("ldmatrix.sync.aligned.m8n8.x4.shared.b16 {%0,%1,%2,%3}, [%4];"
                 : "=r"(r0), "=r"(r1), "=r"(r2), "=r"(r3) : "r"(addr));
}
__device__ __forceinline__ void ldsm_x4_t(uint32_t& r0, uint32_t& r1, uint32_t& r2,
                                          uint32_t& r3, uint32_t addr) {
    asm volatile("ldmatrix.sync.aligned.m8n8.x4.trans.shared.b16 {%0,%1,%2,%3}, [%4];"
                 : "=r"(r0), "=r"(r1), "=r"(r2), "=r"(r3) : "r"(addr));
}
__device__ __forceinline__ void mma_bf16(float* c, const uint32_t* a, const uint32_t* b) {
    asm volatile(
        "mma.sync.aligned.m16n8k16.row.col.f32.bf16.bf16.f32 "
        "{%0,%1,%2,%3}, {%4,%5,%6,%7}, {%8,%9}, {%0,%1,%2,%3};"
        : "+f"(c[0]), "+f"(c[1]), "+f"(c[2]), "+f"(c[3])
        : "r"(a[0]), "r"(a[1]), "r"(a[2]), "r"(a[3]), "r"(b[0]), "r"(b[1]));
}
__device__ __forceinline__ uint32_t pack_bf2(float a, float b) {
    __nv_bfloat162 t = __floats2bfloat162_rn(a, b);
    return *(uint32_t*)&t;
}

// ---------------------------------------------------------------------------
// Split-bf16 HMMA GEMM. B fragments loaded pairwise via ldmatrix.x4
// (lane bit4 selects the second n-tile's 8 rows -> matrices 2,3).
// ---------------------------------------------------------------------------
#define ROW_BYTES   144
#define TILE_BYTES  (128 * ROW_BYTES)     // 18432
#define STAGE_BYTES (4 * TILE_BYTES)
#define GEMM_SMEM   (2 * STAGE_BYTES)

__global__ __launch_bounds__(256, 1)
void mma_gemm_nt(const __nv_bfloat16* __restrict__ Ahi, const __nv_bfloat16* __restrict__ Alo,
                 const __nv_bfloat16* __restrict__ Bhi, const __nv_bfloat16* __restrict__ Blo,
                 float* __restrict__ C, int M, int N, int K) {
    extern __shared__ __align__(128) char smem[];
    const int tid = threadIdx.x;
    const int lane = tid & 31, wid = tid >> 5;
    const int wm = wid & 1, wn = wid >> 1;
    const int m0 = blockIdx.y * 128, n0 = blockIdx.x * 128;
    const int nchunks = K >> 6;

    const __nv_bfloat16* srcs[4] = {Ahi, Alo, Bhi, Blo};

    auto load_stage = [&](int s, int c) {
        const int k0 = c << 6;
        char* st = smem + s * STAGE_BYTES;
#pragma unroll
        for (int o = 0; o < 4; o++) {
            const __nv_bfloat16* src = srcs[o];
            const int rb = (o < 2) ? m0 : n0;
#pragma unroll
            for (int i = 0; i < 4; i++) {
                const int idx = tid + i * 256;
                const int r = idx >> 3, cc = idx & 7;
                const uint32_t dst = smem_u32(st + o * TILE_BYTES + r * ROW_BYTES + cc * 16);
                const void* g = src + (size_t)(rb + r) * K + k0 + cc * 8;
                asm volatile("cp.async.cg.shared.global [%0], [%1], 16;"
                             :: "r"(dst), "l"(g));
            }
        }
        asm volatile("cp.async.commit_group;" ::: "memory");
    };

    float acc[4][4][4];
#pragma unroll
    for (int mt = 0; mt < 4; mt++)
#pragma unroll
        for (int nt = 0; nt < 4; nt++)
#pragma unroll
            for (int e = 0; e < 4; e++) acc[mt][nt][e] = 0.f;

    load_stage(0, 0);

    for (int c = 0; c < nchunks; c++) {
        const int s = c & 1;
        const bool has_next = (c + 1 < nchunks);
        if (has_next) load_stage(s ^ 1, c + 1);
        if (has_next) asm volatile("cp.async.wait_group 1;" ::: "memory");
        else          asm volatile("cp.async.wait_group 0;" ::: "memory");
        __syncthreads();

        const char* st = smem + s * STAGE_BYTES;
        const uint32_t aBaseH = smem_u32(st) +
            (wm * 64 + (lane & 15)) * ROW_BYTES + ((lane >> 4) & 1) * 16;
        const uint32_t aBaseL = aBaseH + TILE_BYTES;
        // merged-pair B base: lane bit3 = k-half, bit4 = n-tile parity (rows +8)
        const uint32_t bBase4H = smem_u32(st + 2 * TILE_BYTES) +
            (wn * 32 + (lane & 7) + ((lane >> 4) & 1) * 8) * ROW_BYTES +
            ((lane >> 3) & 1) * 16;
        const uint32_t bBase4L = bBase4H + TILE_BYTES;

#pragma unroll
        for (int ks = 0; ks < 4; ks++) {
            uint32_t ah[4][4], al[4][4];
#pragma unroll
            for (int mt = 0; mt < 4; mt++) {
                const uint32_t off = mt * 16 * ROW_BYTES + ks * 32;
                ldsm_x4(ah[mt][0], ah[mt][1], ah[mt][2], ah[mt][3], aBaseH + off);
                ldsm_x4(al[mt][0], al[mt][1], al[mt][2], al[mt][3], aBaseL + off);
            }
#pragma unroll
            for (int nt2 = 0; nt2 < 2; nt2++) {
                uint32_t bh4[4], bl4[4];
                const uint32_t off = nt2 * 16 * ROW_BYTES + ks * 32;
                ldsm_x4(bh4[0], bh4[1], bh4[2], bh4[3], bBase4H + off);
                ldsm_x4(bl4[0], bl4[1], bl4[2], bl4[3], bBase4L + off);
#pragma unroll
                for (int mt = 0; mt < 4; mt++) {
                    mma_bf16(acc[mt][2*nt2],   ah[mt], bh4);
                    mma_bf16(acc[mt][2*nt2],   ah[mt], bl4);
                    mma_bf16(acc[mt][2*nt2],   al[mt], bh4);
                    mma_bf16(acc[mt][2*nt2+1], ah[mt], bh4 + 2);
                    mma_bf16(acc[mt][2*nt2+1], ah[mt], bl4 + 2);
                    mma_bf16(acc[mt][2*nt2+1], al[mt], bh4 + 2);
                }
            }
        }
        __syncthreads();
    }

#pragma unroll
    for (int mt = 0; mt < 4; mt++)
#pragma unroll
        for (int nt = 0; nt < 4; nt++) {
            const int row = m0 + wm * 64 + mt * 16 + (lane >> 2);
            const int col = n0 + wn * 32 + nt * 8 + (lane & 3) * 2;
            *(float2*)&C[(size_t)row * N + col] =
                make_float2(acc[mt][nt][0], acc[mt][nt][1]);
            *(float2*)&C[(size_t)(row + 8) * N + col] =
                make_float2(acc[mt][nt][2], acc[mt][nt][3]);
        }
}

// ---------------------------------------------------------------------------
// RoPE + split to bf16 hi/lo: g_qkv [B,S,3,H,DK] -> qh/ql/kh/kl/vh/vl [B,H,S,DK]
// q pre-scaled by 1/8.
// ---------------------------------------------------------------------------
__global__ __launch_bounds__(256)
void rope_split_kernel(const float* __restrict__ qkv, const int* __restrict__ pos,
                       __nv_bfloat16* __restrict__ qh, __nv_bfloat16* __restrict__ ql,
                       __nv_bfloat16* __restrict__ kh, __nv_bfloat16* __restrict__ kl,
                       __nv_bfloat16* __restrict__ vh, __nv_bfloat16* __restrict__ vl) {
    const int idx = blockIdx.x * 256 + threadIdx.x;
    const int i = idx & 31;
    const int h = (idx >> 5) & 15;
    const int s = (idx >> 9) & 2047;
    const int b = idx >> 20;

    const size_t base = ((size_t)(b * SEQ + s)) * QKVD + h * DK + 2 * i;
    const float q1 = qkv[base],         q2 = qkv[base + 1];
    const float k1 = qkv[base + DIM],   k2 = qkv[base + DIM + 1];
    const float v1 = qkv[base + 2*DIM], v2 = qkv[base + 2*DIM + 1];

    const float p = (float)pos[s];
    const float freq = exp2f(-(float)i * 0.41524101186092026f);
    float sn, cs;
    sincosf(p * freq, &sn, &cs);

    const float qe = 0.125f * (q1 * cs - q2 * sn);
    const float qo = 0.125f * (q1 * sn + q2 * cs);
    const float ke = k1 * cs - k2 * sn;
    const float ko = k1 * sn + k2 * cs;

    const size_t ob = ((size_t)((b * HEADS + h) * SEQ + s)) * DK + 2 * i;
#define WRSPLIT(HI, LO, A, B)                                              \
    {                                                                      \
        __nv_bfloat162 h2 = __floats2bfloat162_rn((A), (B));               \
        float2 f = __bfloat1622float2(h2);                                 \
        __nv_bfloat162 l2 = __floats2bfloat162_rn((A) - f.x, (B) - f.y);   \
        *(__nv_bfloat162*)((HI) + ob) = h2;                                \
        *(__nv_bfloat162*)((LO) + ob) = l2;                                \
    }
    WRSPLIT(qh, ql, qe, qo);
    WRSPLIT(kh, kl, ke, ko);
    WRSPLIT(vh, vl, v1, v2);
#undef WRSPLIT
}

// ---------------------------------------------------------------------------
// Tensor-core causal flash attention, split-bf16 (3-term) for S and PV.
// Q fragments hoisted out of the kt loop; K/V loaded pairwise via x4 ldmatrix.
// qt reversed (LPT): heaviest tiles first.
// ---------------------------------------------------------------------------
#define AROW 144
#define ATILE (128 * AROW)                // 18432
#define AQ_BYTES (2 * ATILE)              // Qh, Ql
#define AKV_STAGE (4 * ATILE)             // Kh, Kl, Vh, Vl
#define ATTN_SMEM (AQ_BYTES + 2 * AKV_STAGE)  // 184320

__global__ __launch_bounds__(256, 1)
void attn_mma_kernel(const __nv_bfloat16* __restrict__ qh, const __nv_bfloat16* __restrict__ ql,
                     const __nv_bfloat16* __restrict__ kh, const __nv_bfloat16* __restrict__ kl,
                     const __nv_bfloat16* __restrict__ vh, const __nv_bfloat16* __restrict__ vl,
                     __nv_bfloat16* __restrict__ aohi, __nv_bfloat16* __restrict__ aolo) {
    extern __shared__ __align__(128) char sm2[];
    const int qt = (SEQ / 128) - 1 - blockIdx.x;   // LPT: heavy tiles first
    const int h = blockIdx.y, b = blockIdx.z;
    const int tid = threadIdx.x, lane = tid & 31, wid = tid >> 5;
    const size_t bh = (size_t)(b * HEADS + h) * SEQ;

    // ---- Q tile (hi/lo), part of async group 0 ----
#pragma unroll
    for (int i = 0; i < 4; i++) {
        const int idx = tid + i * 256;
        const int r = idx >> 3, c = idx & 7;
        const uint32_t d = smem_u32(sm2 + r * AROW + c * 16);
        const size_t g = (bh + (size_t)(qt * 128 + r)) * DK + c * 8;
        asm volatile("cp.async.cg.shared.global [%0], [%1], 16;" :: "r"(d), "l"(qh + g));
        asm volatile("cp.async.cg.shared.global [%0], [%1], 16;" :: "r"(d + ATILE), "l"(ql + g));
    }

    auto load_kv = [&](int s, int j) {
        char* st = sm2 + AQ_BYTES + s * AKV_STAGE;
#pragma unroll
        for (int i = 0; i < 4; i++) {
            const int idx = tid + i * 256;
            const int r = idx >> 3, c = idx & 7;
            const uint32_t d0 = smem_u32(st + r * AROW + c * 16);
            const size_t g = (bh + (size_t)(j * 128 + r)) * DK + c * 8;
            asm volatile("cp.async.cg.shared.global [%0], [%1], 16;" :: "r"(d0), "l"(kh + g));
            asm volatile("cp.async.cg.shared.global [%0], [%1], 16;" :: "r"(d0 + ATILE), "l"(kl + g));
            asm volatile("cp.async.cg.shared.global [%0], [%1], 16;" :: "r"(d0 + 2*ATILE), "l"(vh + g));
            asm volatile("cp.async.cg.shared.global [%0], [%1], 16;" :: "r"(d0 + 3*ATILE), "l"(vl + g));
        }
        asm volatile("cp.async.commit_group;" ::: "memory");
    };
    load_kv(0, 0);   // commits group 0 (includes Q)

    float O[8][4];
#pragma unroll
    for (int nt = 0; nt < 8; nt++)
#pragma unroll
        for (int e = 0; e < 4; e++) O[nt][e] = 0.f;
    float mrow[2] = {-1e30f, -1e30f}, lrow[2] = {0.f, 0.f};

    const uint32_t qB = smem_u32(sm2) + (wid * 16 + (lane & 15)) * AROW + ((lane >> 4) & 1) * 16;

    // Q fragments (hi/lo), loaded once after the first stage arrives
    uint32_t qfh[4][4], qfl[4][4];

    for (int kt = 0; kt <= qt; kt++) {
        const int s = kt & 1;
        const bool has_next = (kt < qt);
        if (has_next) load_kv(s ^ 1, kt + 1);
        if (has_next) asm volatile("cp.async.wait_group 1;" ::: "memory");
        else          asm volatile("cp.async.wait_group 0;" ::: "memory");
        __syncthreads();

        if (kt == 0) {
#pragma unroll
            for (int ks = 0; ks < 4; ks++) {
                ldsm_x4(qfh[ks][0], qfh[ks][1], qfh[ks][2], qfh[ks][3], qB + ks * 32);
                ldsm_x4(qfl[ks][0], qfl[ks][1], qfl[ks][2], qfl[ks][3], qB + ATILE + ks * 32);
            }
        }

        const char* st = sm2 + AQ_BYTES + s * AKV_STAGE;
        // merged-pair K base: lane bit3 = k-half, bit4 = n-tile parity (rows +8)
        const uint32_t kB4 = smem_u32(st) +
            ((lane & 7) + ((lane >> 4) & 1) * 8) * AROW + ((lane >> 3) & 1) * 16;
        // merged-pair V base: lane bit4 = second d-tile (cols +16B)
        const uint32_t vB4 = smem_u32(st + 2 * ATILE) +
            (lane & 15) * AROW + ((lane >> 4) & 1) * 16;

        // ---- S = Q K^T (split 3-term), K pairs via x4 ----
        float sacc[16][4];
#pragma unroll
        for (int nt = 0; nt < 16; nt++)
#pragma unroll
            for (int e = 0; e < 4; e++) sacc[nt][e] = 0.f;

#pragma unroll
        for (int nt2 = 0; nt2 < 8; nt2++) {
            const uint32_t off = (uint32_t)(nt2 * 16 * AROW);
#pragma unroll
            for (int ks = 0; ks < 4; ks++) {
                uint32_t kh4[4], kl4[4];
                ldsm_x4(kh4[0], kh4[1], kh4[2], kh4[3], kB4 + off + ks * 32);
                ldsm_x4(kl4[0], kl4[1], kl4[2], kl4[3], kB4 + ATILE + off + ks * 32);
                mma_bf16(sacc[2*nt2],   qfh[ks], kh4);
                mma_bf16(sacc[2*nt2],   qfh[ks], kl4);
                mma_bf16(sacc[2*nt2],   qfl[ks], kh4);
                mma_bf16(sacc[2*nt2+1], qfh[ks], kh4 + 2);
                mma_bf16(sacc[2*nt2+1], qfh[ks], kl4 + 2);
                mma_bf16(sacc[2*nt2+1], qfl[ks], kh4 + 2);
            }
        }

        // ---- causal mask on diagonal tile ----
        if (kt == qt) {
            const int r0 = wid * 16 + (lane >> 2);
            const int c0 = 2 * (lane & 3);
#pragma unroll
            for (int nt = 0; nt < 16; nt++) {
                const int cb = nt * 8 + c0;
                if (cb     > r0)     sacc[nt][0] = -1e30f;
                if (cb + 1 > r0)     sacc[nt][1] = -1e30f;
                if (cb     > r0 + 8) sacc[nt][2] = -1e30f;
                if (cb + 1 > r0 + 8) sacc[nt][3] = -1e30f;
            }
        }

        // ---- online softmax (per-warp; quad-lane reductions) ----
#pragma unroll
        for (int rho = 0; rho < 2; rho++) {
            float mx = -1e30f;
#pragma unroll
            for (int nt = 0; nt < 16; nt++)
                mx = fmaxf(mx, fmaxf(sacc[nt][2*rho], sacc[nt][2*rho+1]));
            mx = fmaxf(mx, __shfl_xor_sync(0xffffffffu, mx, 1));
            mx = fmaxf(mx, __shfl_xor_sync(0xffffffffu, mx, 2));
            const float mn = fmaxf(mrow[rho], mx);
            const float fac = __expf(mrow[rho] - mn);
            mrow[rho] = mn;
            float sum = 0.f;
#pragma unroll
            for (int nt = 0; nt < 16; nt++) {
                const float p0 = __expf(sacc[nt][2*rho]   - mn);
                const float p1 = __expf(sacc[nt][2*rho+1] - mn);
                sacc[nt][2*rho] = p0; sacc[nt][2*rho+1] = p1;
                sum += p0 + p1;
            }
            sum += __shfl_xor_sync(0xffffffffu, sum, 1);
            sum += __shfl_xor_sync(0xffffffffu, sum, 2);
            lrow[rho] = lrow[rho] * fac + sum;
#pragma unroll
            for (int nt = 0; nt < 8; nt++) {
                O[nt][2*rho]   *= fac;
                O[nt][2*rho+1] *= fac;
            }
        }

        // ---- O += P V (split 3-term; P split in-register; V pairs via x4.trans) ----
#pragma unroll
        for (int ks = 0; ks < 8; ks++) {
            const int t0 = 2 * ks, t1 = t0 + 1;
            uint32_t pah[4], pal[4];
            pah[0] = pack_bf2(sacc[t0][0], sacc[t0][1]);
            pah[1] = pack_bf2(sacc[t0][2], sacc[t0][3]);
            pah[2] = pack_bf2(sacc[t1][0], sacc[t1][1]);
            pah[3] = pack_bf2(sacc[t1][2], sacc[t1][3]);
            {
                float2 f0 = __bfloat1622float2(*(__nv_bfloat162*)&pah[0]);
                float2 f1 = __bfloat1622float2(*(__nv_bfloat162*)&pah[1]);
                float2 f2 = __bfloat1622float2(*(__nv_bfloat162*)&pah[2]);
                float2 f3 = __bfloat1622float2(*(__nv_bfloat162*)&pah[3]);
                pal[0] = pack_bf2(sacc[t0][0] - f0.x, sacc[t0][1] - f0.y);
                pal[1] = pack_bf2(sacc[t0][2] - f1.x, sacc[t0][3] - f1.y);
                pal[2] = pack_bf2(sacc[t1][0] - f2.x, sacc[t1][1] - f2.y);
                pal[3] = pack_bf2(sacc[t1][2] - f3.x, sacc[t1][3] - f3.y);
            }
            const uint32_t vrow = vB4 + (uint32_t)(ks * 16 * AROW);
#pragma unroll
            for (int dt2 = 0; dt2 < 4; dt2++) {
                uint32_t vh4[4], vl4[4];
                ldsm_x4_t(vh4[0], vh4[1], vh4[2], vh4[3], vrow + dt2 * 32);
                ldsm_x4_t(vl4[0], vl4[1], vl4[2], vl4[3], vrow + ATILE + dt2 * 32);
                mma_bf16(O[2*dt2],   pah, vh4);
                mma_bf16(O[2*dt2],   pah, vl4);
                mma_bf16(O[2*dt2],   pal, vh4);
                mma_bf16(O[2*dt2+1], pah, vh4 + 2);
                mma_bf16(O[2*dt2+1], pah, vl4 + 2);
                mma_bf16(O[2*dt2+1], pal, vh4 + 2);
            }
        }
        __syncthreads();
    }

    // ---- epilogue: normalize, split to bf16 hi/lo, write ao ----
#pragma unroll
    for (int rho = 0; rho < 2; rho++) {
        const float inv = 1.0f / lrow[rho];
        const int srow = qt * 128 + wid * 16 + (lane >> 2) + rho * 8;
        const size_t rowoff = ((size_t)b * SEQ + srow) * DIM + h * 64 + 2 * (lane & 3);
#pragma unroll
        for (int nt = 0; nt < 8; nt++) {
            const float o0 = O[nt][2*rho] * inv, o1 = O[nt][2*rho+1] * inv;
            __nv_bfloat162 h2 = __floats2bfloat162_rn(o0, o1);
            float2 f = __bfloat1622float2(h2);
            __nv_bfloat162 l2 = __floats2bfloat162_rn(o0 - f.x, o1 - f.y);
            *(__nv_bfloat162*)(aohi + rowoff + nt * 8) = h2;
            *(__nv_bfloat162*)(aolo + rowoff + nt * 8) = l2;
        }
    }
}

// ---------------------------------------------------------------------------
extern "C" void kernel_launch(void* const* d_in, const int* in_sizes, int n_in,
                              void* d_out, int out_size) {
    const float* x    = (const float*)d_in[0];
    const int*   pos  = (const int*)d_in[1];
    const float* wqkv = (const float*)d_in[2];
    const float* wout = (const float*)d_in[3];
    float* out = (float*)d_out;

    float* qkv;
    __nv_bfloat16 *xhi, *xlo, *w1hi, *w1lo, *w2hi, *w2lo, *aohi, *aolo;
    __nv_bfloat16 *pqh, *pql, *pkh, *pkl, *pvh, *pvl;
    cudaGetSymbolAddress((void**)&qkv,  g_qkv);
    cudaGetSymbolAddress((void**)&xhi,  g_xhi);
    cudaGetSymbolAddress((void**)&xlo,  g_xlo);
    cudaGetSymbolAddress((void**)&w1hi, g_w1hi);
    cudaGetSymbolAddress((void**)&w1lo, g_w1lo);
    cudaGetSymbolAddress((void**)&w2hi, g_w2hi);
    cudaGetSymbolAddress((void**)&w2lo, g_w2lo);
    cudaGetSymbolAddress((void**)&aohi, g_aohi);
    cudaGetSymbolAddress((void**)&aolo, g_aolo);
    cudaGetSymbolAddress((void**)&pqh,  g_qh);
    cudaGetSymbolAddress((void**)&pql,  g_ql);
    cudaGetSymbolAddress((void**)&pkh,  g_kh);
    cudaGetSymbolAddress((void**)&pkl,  g_kl);
    cudaGetSymbolAddress((void**)&pvh,  g_vh);
    cudaGetSymbolAddress((void**)&pvl,  g_vl);

    cudaFuncSetAttribute(mma_gemm_nt, cudaFuncAttributeMaxDynamicSharedMemorySize,
                         GEMM_SMEM);
    cudaFuncSetAttribute(attn_mma_kernel, cudaFuncAttributeMaxDynamicSharedMemorySize,
                         ATTN_SMEM);

    // 0) split inputs/weights to bf16 hi/lo
    split_bf16_kernel<<<(MROWS*DIM/4)/256, 256>>>(x,    xhi,  xlo,  MROWS*DIM/4);
    split_bf16_kernel<<<(QKVD*DIM/4)/256,  256>>>(wqkv, w1hi, w1lo, QKVD*DIM/4);
    split_bf16_kernel<<<(DIM*DIM/4)/256,   256>>>(wout, w2hi, w2lo, DIM*DIM/4);

    // 1) QKV projection (tensor cores, split-bf16)
    mma_gemm_nt<<<dim3(QKVD/128, MROWS/128), 256, GEMM_SMEM>>>(
        xhi, xlo, w1hi, w1lo, qkv, MROWS, QKVD, DIM);

    // 2) RoPE + split q/k/v to bf16 hi/lo [B,H,S,DK]
    rope_split_kernel<<<(BATCH * SEQ * HEADS * 32) / 256, 256>>>(
        qkv, pos, pqh, pql, pkh, pkl, pvh, pvl);

    // 3) Tensor-core causal flash attention (writes ao hi/lo directly)
    attn_mma_kernel<<<dim3(SEQ/128, HEADS, BATCH), 256, ATTN_SMEM>>>(
        pqh, pql, pkh, pkl, pvh, pvl, aohi, aolo);

    // 4) Output projection (tensor cores)
    mma_gemm_nt<<<dim3(DIM/128, MROWS/128), 256, GEMM_SMEM>>>(
        aohi, aolo, w2hi, w2lo, out, MROWS, DIM, DIM);
}